// round 1
// baseline (speedup 1.0000x reference)
#include <cuda_runtime.h>
#include <math.h>

// Problem constants (fixed by the reference)
constexpr int BN  = 4;
constexpr int SN  = 2048;
constexpr int DN  = 2048;
constexpr int HN  = 16;
constexpr int DHN = 128;
constexpr int BH  = BN * HN;      // 64
constexpr int MR  = BN * SN;      // 8192 rows for the big GEMMs
constexpr float QK_SCALE = 0.08838834764831845f;  // 1/sqrt(128)

// ---------------- static device scratch (no allocations allowed) ----------------
__device__ float g_Q  [(size_t)BH * SN * DHN];   // [b,h,s,dh]  64 MB
__device__ float g_K  [(size_t)BH * SN * DHN];
__device__ float g_V  [(size_t)BH * SN * DHN];
__device__ float g_P  [(size_t)BH * SN * SN];    // scores -> probs, 1 GiB
__device__ float g_PV [(size_t)BH * SN * DHN];
__device__ float g_SUF[(size_t)BH * SN * DHN];   // suffix sums of V (exclusive: sum_{k>s})
__device__ float g_X  [(size_t)MR * DN];         // merged heads, [B,S,D]

// ---------------- generic 128x128x16 fp32 GEMM ----------------
// C = scale * A @ B (+bias), with optional B-transposed access (C = A @ B^T),
// batched via blockIdx.z (strides sA/sB/sC).
// EPI 0: row-major store + bias       (final projection)
// EPI 1: head-layout store + bias     (Q/K/V projections -> [b,h,s,dh])
// EPI 2: row-major batched store      (scores / PV)
template<int EPI, bool TB>
__global__ void __launch_bounds__(256)
gemm_k(const float* __restrict__ A, const float* __restrict__ Bm,
       const float* __restrict__ bias, float* __restrict__ C,
       int K, int lda, int ldb, int ldc,
       long long sA, long long sB, long long sC, float scale)
{
    __shared__ float As[16][128];
    __shared__ float Bs[16][128];
    const int tid = threadIdx.x;
    const int tx = tid & 15, ty = tid >> 4;
    const int m0 = blockIdx.y * 128, n0 = blockIdx.x * 128;
    const float* Ab = A  + (long long)blockIdx.z * sA;
    const float* Bb = Bm + (long long)blockIdx.z * sB;

    float acc[8][8];
#pragma unroll
    for (int i = 0; i < 8; i++)
#pragma unroll
        for (int j = 0; j < 8; j++) acc[i][j] = 0.f;

    for (int k0 = 0; k0 < K; k0 += 16) {
        // A tile: 128 x 16, stored transposed As[k][m]
        {
            int t = tid;
#pragma unroll
            for (int i = 0; i < 2; i++, t += 256) {
                int r = t >> 2, c4 = t & 3;
                float4 v = *(const float4*)(Ab + (long long)(m0 + r) * lda + (k0 + c4 * 4));
                As[c4 * 4 + 0][r] = v.x; As[c4 * 4 + 1][r] = v.y;
                As[c4 * 4 + 2][r] = v.z; As[c4 * 4 + 3][r] = v.w;
            }
        }
        if (TB) {
            // B is [N,K] row-major (C = A @ B^T): Bs[k][n] = B[n][k]
            int t = tid;
#pragma unroll
            for (int i = 0; i < 2; i++, t += 256) {
                int n = t >> 2, c4 = t & 3;
                float4 v = *(const float4*)(Bb + (long long)(n0 + n) * ldb + (k0 + c4 * 4));
                Bs[c4 * 4 + 0][n] = v.x; Bs[c4 * 4 + 1][n] = v.y;
                Bs[c4 * 4 + 2][n] = v.z; Bs[c4 * 4 + 3][n] = v.w;
            }
        } else {
            // B is [K,N] row-major
            int t = tid;
#pragma unroll
            for (int i = 0; i < 2; i++, t += 256) {
                int r = t >> 5, c4 = t & 31;
                *(float4*)(&Bs[r][c4 * 4]) =
                    *(const float4*)(Bb + (long long)(k0 + r) * ldb + (n0 + c4 * 4));
            }
        }
        __syncthreads();
#pragma unroll
        for (int kk = 0; kk < 16; kk++) {
            float4 a0 = *(const float4*)(&As[kk][ty * 8]);
            float4 a1 = *(const float4*)(&As[kk][ty * 8 + 4]);
            float4 b0 = *(const float4*)(&Bs[kk][tx * 8]);
            float4 b1 = *(const float4*)(&Bs[kk][tx * 8 + 4]);
            float a[8] = {a0.x, a0.y, a0.z, a0.w, a1.x, a1.y, a1.z, a1.w};
            float b[8] = {b0.x, b0.y, b0.z, b0.w, b1.x, b1.y, b1.z, b1.w};
#pragma unroll
            for (int i = 0; i < 8; i++)
#pragma unroll
                for (int j = 0; j < 8; j++)
                    acc[i][j] = fmaf(a[i], b[j], acc[i][j]);
        }
        __syncthreads();
    }

#pragma unroll
    for (int i = 0; i < 8; i++) {
        int m = m0 + ty * 8 + i;
#pragma unroll
        for (int j = 0; j < 8; j++) {
            int n = n0 + tx * 8 + j;
            float v = acc[i][j] * scale;
            if (EPI == 0) {
                if (bias) v += bias[n];
                C[(long long)m * ldc + n] = v;
            } else if (EPI == 1) {
                if (bias) v += bias[n];
                int b = m >> 11, s = m & 2047;     // m = b*S + s
                int h = n >> 7,  dh = n & 127;     // n = h*DH + dh
                C[(((long long)(b * HN + h)) * SN + s) * DHN + dh] = v;
            } else {
                C[(long long)blockIdx.z * sC + (long long)m * ldc + n] = v;
            }
        }
    }
}

// ---------------- full-row softmax, then zero the non-causal (k>q) entries ----------------
__global__ void __launch_bounds__(256)
softmax_causal(float* __restrict__ P)
{
    long long row = blockIdx.x;              // 0 .. BH*S-1
    int q = (int)(row & (SN - 1));
    float* p = P + row * SN;
    int tid = threadIdx.x;
    int lane = tid & 31, wid = tid >> 5;

    float4 v0 = ((const float4*)p)[tid];
    float4 v1 = ((const float4*)p)[tid + 256];

    float mx = fmaxf(fmaxf(fmaxf(v0.x, v0.y), fmaxf(v0.z, v0.w)),
                     fmaxf(fmaxf(v1.x, v1.y), fmaxf(v1.z, v1.w)));
#pragma unroll
    for (int o = 16; o; o >>= 1) mx = fmaxf(mx, __shfl_xor_sync(0xffffffffu, mx, o));

    __shared__ float rmax[8], rsum[8];
    if (lane == 0) rmax[wid] = mx;
    __syncthreads();
    float m = fmaxf(fmaxf(fmaxf(rmax[0], rmax[1]), fmaxf(rmax[2], rmax[3])),
                    fmaxf(fmaxf(rmax[4], rmax[5]), fmaxf(rmax[6], rmax[7])));

    float e[8];
    e[0] = __expf(v0.x - m); e[1] = __expf(v0.y - m);
    e[2] = __expf(v0.z - m); e[3] = __expf(v0.w - m);
    e[4] = __expf(v1.x - m); e[5] = __expf(v1.y - m);
    e[6] = __expf(v1.z - m); e[7] = __expf(v1.w - m);
    float s = ((e[0] + e[1]) + (e[2] + e[3])) + ((e[4] + e[5]) + (e[6] + e[7]));
#pragma unroll
    for (int o = 16; o; o >>= 1) s += __shfl_xor_sync(0xffffffffu, s, o);
    if (lane == 0) rsum[wid] = s;
    __syncthreads();
    float tot = ((rsum[0] + rsum[1]) + (rsum[2] + rsum[3])) +
                ((rsum[4] + rsum[5]) + (rsum[6] + rsum[7]));
    float inv = 1.0f / tot;

    int k0 = tid * 4, k1 = 1024 + tid * 4;
    float4 o0, o1;
    o0.x = (k0 + 0 <= q) ? e[0] * inv : 0.f;
    o0.y = (k0 + 1 <= q) ? e[1] * inv : 0.f;
    o0.z = (k0 + 2 <= q) ? e[2] * inv : 0.f;
    o0.w = (k0 + 3 <= q) ? e[3] * inv : 0.f;
    o1.x = (k1 + 0 <= q) ? e[4] * inv : 0.f;
    o1.y = (k1 + 1 <= q) ? e[5] * inv : 0.f;
    o1.z = (k1 + 2 <= q) ? e[6] * inv : 0.f;
    o1.w = (k1 + 3 <= q) ? e[7] * inv : 0.f;
    ((float4*)p)[tid] = o0;
    ((float4*)p)[tid + 256] = o1;
}

// ---------------- exclusive suffix sums of V along s: SUF[s] = sum_{k>s} V[k] ----------------
__global__ void __launch_bounds__(128)
suffix_k(const float* __restrict__ V, float* __restrict__ SUF)
{
    int bh = blockIdx.x;
    int d = threadIdx.x;
    const float* v = V  + (long long)bh * SN * DHN;
    float*       s = SUF + (long long)bh * SN * DHN;
    float acc = 0.f;
    for (int i = SN - 1; i >= 0; i--) {
        s[(long long)i * DHN + d] = acc;
        acc += v[(long long)i * DHN + d];
    }
}

// ---------------- merge: X[b,s,h*128+dh] = PV[b,h,s,dh] - 1e9 * SUF[b,h,s,dh] ----------------
__global__ void __launch_bounds__(256)
merge_k(const float* __restrict__ PV, const float* __restrict__ SUF, float* __restrict__ X)
{
    long long i = (long long)blockIdx.x * 256 + threadIdx.x;   // over BH*S*DH
    float val = PV[i] - 1e9f * SUF[i];
    int dh = (int)(i & 127);
    long long t = i >> 7;
    int s = (int)(t & 2047);
    t >>= 11;
    int h = (int)(t & 15);
    int b = (int)(t >> 4);
    X[(((long long)b * SN + s) * DN) + h * DHN + dh] = val;
}

// ---------------- launch ----------------
extern "C" void kernel_launch(void* const* d_in, const int* in_sizes, int n_in,
                              void* d_out, int out_size)
{
    const float* q  = (const float*)d_in[0];
    const float* k  = (const float*)d_in[1];
    const float* v  = (const float*)d_in[2];
    const float* Wq = (const float*)d_in[3];
    const float* bq = (const float*)d_in[4];
    const float* Wk = (const float*)d_in[5];
    const float* bk = (const float*)d_in[6];
    const float* Wv = (const float*)d_in[7];
    const float* bv = (const float*)d_in[8];
    const float* Wo = (const float*)d_in[9];
    const float* bo = (const float*)d_in[10];
    // d_in[11] = mask (known causal tril, not needed)
    float* out = (float*)d_out;

    void *pQ, *pK, *pV, *pP, *pPV, *pSUF, *pX;
    cudaGetSymbolAddress(&pQ,  g_Q);
    cudaGetSymbolAddress(&pK,  g_K);
    cudaGetSymbolAddress(&pV,  g_V);
    cudaGetSymbolAddress(&pP,  g_P);
    cudaGetSymbolAddress(&pPV, g_PV);
    cudaGetSymbolAddress(&pSUF,g_SUF);
    cudaGetSymbolAddress(&pX,  g_X);
    float* Qb  = (float*)pQ;   float* Kb = (float*)pK;  float* Vb = (float*)pV;
    float* Pb  = (float*)pP;   float* PVb = (float*)pPV;
    float* SUFb = (float*)pSUF; float* Xb = (float*)pX;

    // 1) Q/K/V projections: [8192,2048] @ [2048,2048] + b  -> head layout
    dim3 gProj(DN / 128, MR / 128);   // (16, 64)
    gemm_k<1, false><<<gProj, 256>>>(q, Wq, bq, Qb, DN, DN, DN, 0, 0, 0, 0, 1.f);
    gemm_k<1, false><<<gProj, 256>>>(k, Wk, bk, Kb, DN, DN, DN, 0, 0, 0, 0, 1.f);
    gemm_k<1, false><<<gProj, 256>>>(v, Wv, bv, Vb, DN, DN, DN, 0, 0, 0, 0, 1.f);

    // 2) scores = Q @ K^T / sqrt(DH), batched over 64 heads
    dim3 gSc(SN / 128, SN / 128, BH); // (16, 16, 64)
    gemm_k<2, true><<<gSc, 256>>>(Qb, Kb, nullptr, Pb,
                                  DHN, DHN, DHN, SN,
                                  (long long)SN * DHN, (long long)SN * DHN,
                                  (long long)SN * SN, QK_SCALE);

    // 3) full-row softmax, zero non-causal entries
    softmax_causal<<<BH * SN, 256>>>(Pb);

    // 4) exclusive suffix sums of V
    suffix_k<<<BH, 128>>>(Vb, SUFb);

    // 5) PV = P @ V, batched over heads
    dim3 gPV(DHN / 128, SN / 128, BH); // (1, 16, 64)
    gemm_k<2, false><<<gPV, 256>>>(Pb, Vb, nullptr, PVb,
                                   SN, SN, DHN, DHN,
                                   (long long)SN * SN, (long long)SN * DHN,
                                   (long long)SN * DHN, 1.f);

    // 6) merge heads + suffix correction -> [B,S,D]
    merge_k<<<(BH * SN * DHN) / 256, 256>>>(PVb, SUFb, Xb);

    // 7) output projection -> d_out
    gemm_k<0, false><<<gProj, 256>>>(Xb, Wo, bo, out, DN, DN, DN, DN, 0, 0, 0, 1.f);
}

// round 3
// speedup vs baseline: 4.5598x; 4.5598x over previous
#include <cuda_runtime.h>
#include <cstdint>
#include <math.h>

// ---------------- problem constants ----------------
constexpr int BN  = 4;
constexpr int SN  = 2048;
constexpr int DN  = 2048;
constexpr int HN  = 16;
constexpr int DHN = 128;
constexpr int BH  = BN * HN;      // 64
constexpr int MR  = BN * SN;      // 8192
constexpr float QK_SCALE = 0.08838834764831845f;

// ---------------- static device scratch ----------------
__device__ float g_qr [(size_t)MR * DN];
__device__ float g_kr [(size_t)MR * DN];
__device__ float g_vr [(size_t)MR * DN];
__device__ float g_Wtq[(size_t)DN * DN];
__device__ float g_Wtk[(size_t)DN * DN];
__device__ float g_Wtv[(size_t)DN * DN];
__device__ float g_Wto[(size_t)DN * DN];
__device__ float g_Q  [(size_t)BH * SN * DHN];   // [bh,s,dh]
__device__ float g_K  [(size_t)BH * SN * DHN];
__device__ float g_Vh [(size_t)BH * SN * DHN];   // [bh,s,dh]
__device__ float g_Vt [(size_t)BH * DHN * SN];   // [bh,dh,s]
__device__ float g_P  [(size_t)BH * SN * SN];    // 1 GiB
__device__ float g_PV [(size_t)BH * SN * DHN];
__device__ float g_SEG[(size_t)BH * 16 * DHN];
__device__ float g_SUF[(size_t)BH * SN * DHN];
__device__ float g_X  [(size_t)MR * DN];

// ---------------- helpers ----------------
__device__ __forceinline__ uint32_t smem_u32(const void* p) {
    uint32_t a;
    asm("{ .reg .u64 t; cvta.to.shared.u64 t, %1; cvt.u32.u64 %0, t; }" : "=r"(a) : "l"(p));
    return a;
}
__device__ __forceinline__ float rnd_tf32(float x) {
    uint32_t u;
    asm("cvt.rna.tf32.f32 %0, %1;" : "=r"(u) : "f"(x));
    return __uint_as_float(u);
}
__device__ __forceinline__ void cp_async16(uint32_t dst, const void* src) {
    asm volatile("cp.async.cg.shared.global [%0], [%1], 16;" :: "r"(dst), "l"(src));
}
__device__ __forceinline__ void cp_commit() { asm volatile("cp.async.commit_group;"); }
__device__ __forceinline__ void cp_wait0()  { asm volatile("cp.async.wait_group 0;"); }
__device__ __forceinline__ void cp_wait1()  { asm volatile("cp.async.wait_group 1;"); }

__device__ __forceinline__ uint32_t swz(uint32_t off) {
    return off ^ ((off >> 3) & 0x70);
}
__device__ __forceinline__ void ldsm4(uint32_t& r0, uint32_t& r1, uint32_t& r2, uint32_t& r3,
                                      uint32_t addr) {
    asm volatile("ldmatrix.sync.aligned.m8n8.x4.shared.b16 {%0,%1,%2,%3}, [%4];"
        : "=r"(r0), "=r"(r1), "=r"(r2), "=r"(r3) : "r"(addr));
}
__device__ __forceinline__ void mma_1688(float* c, const uint32_t* a, const uint32_t* b) {
    asm volatile("mma.sync.aligned.m16n8k8.row.col.f32.tf32.tf32.f32 "
        "{%0,%1,%2,%3},{%4,%5,%6,%7},{%8,%9},{%0,%1,%2,%3};"
        : "+f"(c[0]), "+f"(c[1]), "+f"(c[2]), "+f"(c[3])
        : "r"(a[0]), "r"(a[1]), "r"(a[2]), "r"(a[3]), "r"(b[0]), "r"(b[1]));
}

// ---------------- tf32 mma.sync GEMM ----------------
// D[m,n] = scale * sum_k A[m,k] * B[n,k]   (A,B K-major fp32-as-tf32)
// CTA tile 128x128, K chunk 32. 8 warps (2x4), warp tile 64x32.
// EPI: 0 out-proj(+bias), 1 QK-proj(+bias,rnd,head layout),
//      2 V-proj(+bias,rnd,head layout + transposed), 3 scores(*scale,batched),
//      4 PV(batched)
template<int EPI>
__global__ void __launch_bounds__(256, 2)
mma_gemm(const float* __restrict__ A, const float* __restrict__ Bm,
         const float* __restrict__ bias, float* __restrict__ C, float* __restrict__ C2,
         int K, int lda, int ldb, long long sA, long long sB, float scale)
{
    extern __shared__ char smem[];
    const uint32_t sb = smem_u32(smem);
    // layout: A bufs [0,16K),[16K,32K)  B bufs [32K,48K),[48K,64K)
    const int tid = threadIdx.x, wid = tid >> 5, lane = tid & 31;
    const int wm = wid >> 2, wn = wid & 3;           // warp grid 2x4
    const int m0 = blockIdx.y * 128, n0 = blockIdx.x * 128;
    const float* Ab = A  + (long long)blockIdx.z * sA;
    const float* Bb = Bm + (long long)blockIdx.z * sB;

    float acc[64];
#pragma unroll
    for (int i = 0; i < 64; i++) acc[i] = 0.f;

    const int CC = K >> 5;

    auto load_chunk = [&](int buf, int c) {
        int k0 = c << 5;
#pragma unroll
        for (int i = 0; i < 4; i++) {            // A: 128 rows x 8 x 16B
            int u = tid + i * 256;
            int r = u >> 3, ku = u & 7;
            cp_async16(sb + buf * 16384 + swz(r * 128 + ku * 16),
                       Ab + (size_t)(m0 + r) * lda + k0 + ku * 4);
        }
#pragma unroll
        for (int i = 0; i < 4; i++) {            // B: 128 rows x 8 x 16B
            int u = tid + i * 256;
            int r = u >> 3, ku = u & 7;
            cp_async16(sb + 32768 + buf * 16384 + swz(r * 128 + ku * 16),
                       Bb + (size_t)(n0 + r) * ldb + k0 + ku * 4);
        }
        cp_commit();
    };

    // per-thread ldmatrix bases
    // A fragment (m16n8k8): mat0=(m+0..7,klo) mat1=(m+8..15,klo) mat2=(m+0..7,khi) mat3=(m+8..15,khi)
    const int r8 = lane & 7;
    const int aRow8 = (lane >> 3) & 1;           // +8 rows for mats 1,3
    const int aKh   = (lane >> 4) & 1;           // k-hi 16B for mats 2,3
    uint32_t aBase[4], aSx[4];
#pragma unroll
    for (int mt = 0; mt < 4; mt++) {
        int m = wm * 64 + mt * 16 + aRow8 * 8 + r8;
        aBase[mt] = m * 128;
        aSx[mt] = (m & 7) << 4;
    }
    // B fragment: for n-tile pair p: mat0=(n+0..7,klo) mat1=(n+0..7,khi) mat2=(n+8..15,klo) mat3=(n+8..15,khi)
    const int bKh   = (lane >> 3) & 1;
    const int bRow8 = (lane >> 4) & 1;
    uint32_t bBase[2], bSx[2];
#pragma unroll
    for (int p = 0; p < 2; p++) {
        int n = wn * 32 + p * 16 + bRow8 * 8 + r8;
        bBase[p] = 32768 + n * 128;
        bSx[p] = (n & 7) << 4;
    }

    load_chunk(0, 0);
    for (int c = 0; c < CC; c++) {
        if (c + 1 < CC) { load_chunk((c + 1) & 1, c + 1); cp_wait1(); }
        else            { cp_wait0(); }
        __syncthreads();
        const uint32_t bufA = sb + (c & 1) * 16384;
        const uint32_t bufB = sb + (c & 1) * 16384;   // B base already includes +32768
#pragma unroll
        for (int kk = 0; kk < 4; kk++) {
            uint32_t a[4][4];
            const uint32_t kofA = ((uint32_t)(kk << 5)) | (aKh << 4);
#pragma unroll
            for (int mt = 0; mt < 4; mt++)
                ldsm4(a[mt][0], a[mt][1], a[mt][2], a[mt][3],
                      bufA + aBase[mt] + (kofA ^ aSx[mt]));
            uint32_t b[4][2];
            const uint32_t kofB = ((uint32_t)(kk << 5)) | (bKh << 4);
#pragma unroll
            for (int p = 0; p < 2; p++) {
                uint32_t r0, r1, r2, r3;
                ldsm4(r0, r1, r2, r3, bufB + bBase[p] + (kofB ^ bSx[p]));
                b[p * 2 + 0][0] = r0; b[p * 2 + 0][1] = r1;
                b[p * 2 + 1][0] = r2; b[p * 2 + 1][1] = r3;
            }
#pragma unroll
            for (int mt = 0; mt < 4; mt++)
#pragma unroll
                for (int nt = 0; nt < 4; nt++)
                    mma_1688(&acc[(mt * 4 + nt) * 4], a[mt], b[nt]);
        }
        __syncthreads();
    }

    // epilogue
    const int gid = lane >> 2, tig = lane & 3;
    auto store2 = [&](int m, int n, float x, float y) {
        if (EPI == 0) {
            float2 bb = *(const float2*)(bias + n);
            float2 v = make_float2(x + bb.x, y + bb.y);
            *(float2*)(C + (size_t)m * DN + n) = v;
        } else if (EPI == 1 || EPI == 2) {
            float2 bb = *(const float2*)(bias + n);
            float vx = rnd_tf32(x + bb.x), vy = rnd_tf32(y + bb.y);
            int bi = m >> 11, s = m & 2047;
            int h = n >> 7, dh = n & 127;
            size_t hb = (size_t)(bi * HN + h);
            *(float2*)(C + (hb * SN + s) * DHN + dh) = make_float2(vx, vy);
            if (EPI == 2) {
                C2[(hb * DHN + dh + 0) * SN + s] = vx;
                C2[(hb * DHN + dh + 1) * SN + s] = vy;
            }
        } else if (EPI == 3) {
            *(float2*)(C + (size_t)blockIdx.z * SN * SN + (size_t)m * SN + n) =
                make_float2(x * scale, y * scale);
        } else {
            *(float2*)(C + (size_t)blockIdx.z * SN * DHN + (size_t)m * DHN + n) =
                make_float2(x, y);
        }
    };
#pragma unroll
    for (int mt = 0; mt < 4; mt++) {
        int m = m0 + wm * 64 + mt * 16 + gid;
#pragma unroll
        for (int nt = 0; nt < 4; nt++) {
            int n = n0 + wn * 32 + nt * 8 + 2 * tig;
            const float* cc = &acc[(mt * 4 + nt) * 4];
            store2(m,     n, cc[0], cc[1]);
            store2(m + 8, n, cc[2], cc[3]);
        }
    }
}

// ---------------- pre-pass: round / transpose ----------------
__global__ void __launch_bounds__(256)
round_copy(const float* __restrict__ x, float* __restrict__ y)
{
    int i = blockIdx.x * 256 + threadIdx.x;
    float4 v = ((const float4*)x)[i];
    v.x = rnd_tf32(v.x); v.y = rnd_tf32(v.y);
    v.z = rnd_tf32(v.z); v.w = rnd_tf32(v.w);
    ((float4*)y)[i] = v;
}

__global__ void __launch_bounds__(256)
transpose_round(const float* __restrict__ W, float* __restrict__ Wt)
{
    __shared__ float t[32][33];
    int k0 = blockIdx.x * 32, n0 = blockIdx.y * 32;
    int tx = threadIdx.x & 31, ty = threadIdx.x >> 5;
#pragma unroll
    for (int j = ty; j < 32; j += 8)
        t[j][tx] = W[(size_t)(k0 + j) * DN + n0 + tx];
    __syncthreads();
#pragma unroll
    for (int j = ty; j < 32; j += 8)
        Wt[(size_t)(n0 + j) * DN + k0 + tx] = rnd_tf32(t[tx][j]);
}

// ---------------- softmax (full row) + causal zero + tf32 round ----------------
__global__ void __launch_bounds__(256)
softmax_causal(float* __restrict__ P)
{
    long long row = blockIdx.x;
    int q = (int)(row & (SN - 1));
    float* p = P + row * SN;
    int tid = threadIdx.x, lane = tid & 31, wid = tid >> 5;

    float4 v0 = ((const float4*)p)[tid];
    float4 v1 = ((const float4*)p)[tid + 256];
    float mx = fmaxf(fmaxf(fmaxf(v0.x, v0.y), fmaxf(v0.z, v0.w)),
                     fmaxf(fmaxf(v1.x, v1.y), fmaxf(v1.z, v1.w)));
#pragma unroll
    for (int o = 16; o; o >>= 1) mx = fmaxf(mx, __shfl_xor_sync(0xffffffffu, mx, o));
    __shared__ float rmax[8], rsum[8];
    if (lane == 0) rmax[wid] = mx;
    __syncthreads();
    float m = fmaxf(fmaxf(fmaxf(rmax[0], rmax[1]), fmaxf(rmax[2], rmax[3])),
                    fmaxf(fmaxf(rmax[4], rmax[5]), fmaxf(rmax[6], rmax[7])));
    float e[8];
    e[0] = __expf(v0.x - m); e[1] = __expf(v0.y - m);
    e[2] = __expf(v0.z - m); e[3] = __expf(v0.w - m);
    e[4] = __expf(v1.x - m); e[5] = __expf(v1.y - m);
    e[6] = __expf(v1.z - m); e[7] = __expf(v1.w - m);
    float s = ((e[0] + e[1]) + (e[2] + e[3])) + ((e[4] + e[5]) + (e[6] + e[7]));
#pragma unroll
    for (int o = 16; o; o >>= 1) s += __shfl_xor_sync(0xffffffffu, s, o);
    if (lane == 0) rsum[wid] = s;
    __syncthreads();
    float tot = ((rsum[0] + rsum[1]) + (rsum[2] + rsum[3])) +
                ((rsum[4] + rsum[5]) + (rsum[6] + rsum[7]));
    float inv = 1.0f / tot;

    int k0 = tid * 4, k1 = 1024 + tid * 4;
    float4 o0, o1;
    o0.x = (k0 + 0 <= q) ? rnd_tf32(e[0] * inv) : 0.f;
    o0.y = (k0 + 1 <= q) ? rnd_tf32(e[1] * inv) : 0.f;
    o0.z = (k0 + 2 <= q) ? rnd_tf32(e[2] * inv) : 0.f;
    o0.w = (k0 + 3 <= q) ? rnd_tf32(e[3] * inv) : 0.f;
    o1.x = (k1 + 0 <= q) ? rnd_tf32(e[4] * inv) : 0.f;
    o1.y = (k1 + 1 <= q) ? rnd_tf32(e[5] * inv) : 0.f;
    o1.z = (k1 + 2 <= q) ? rnd_tf32(e[6] * inv) : 0.f;
    o1.w = (k1 + 3 <= q) ? rnd_tf32(e[7] * inv) : 0.f;
    ((float4*)p)[tid] = o0;
    ((float4*)p)[tid + 256] = o1;
}

// ---------------- suffix sums of V (two-pass segmented) ----------------
__global__ void __launch_bounds__(128)
suf_pass1(const float* __restrict__ Vh, float* __restrict__ seg)
{
    int bh = blockIdx.x, sg = blockIdx.y, d = threadIdx.x;
    const float* v = Vh + ((size_t)bh * SN + sg * 128) * DHN + d;
    float a = 0.f;
#pragma unroll 8
    for (int i = 0; i < 128; i++) a += v[(size_t)i * DHN];
    seg[((size_t)bh * 16 + sg) * DHN + d] = a;
}

__global__ void __launch_bounds__(128)
suf_pass2(const float* __restrict__ Vh, const float* __restrict__ seg,
          float* __restrict__ SUF)
{
    int bh = blockIdx.x, sg = blockIdx.y, d = threadIdx.x;
    float off = 0.f;
    for (int j = sg + 1; j < 16; j++) off += seg[((size_t)bh * 16 + j) * DHN + d];
    const float* v = Vh + ((size_t)bh * SN + sg * 128) * DHN + d;
    float* o = SUF + ((size_t)bh * SN + sg * 128) * DHN + d;
    float a = off;
    for (int i = 127; i >= 0; i--) {
        o[(size_t)i * DHN] = a;
        a += v[(size_t)i * DHN];
    }
}

// ---------------- merge heads + suffix correction (rounded) ----------------
__global__ void __launch_bounds__(256)
merge_k(const float* __restrict__ PV, const float* __restrict__ SUF, float* __restrict__ X)
{
    long long i = (long long)blockIdx.x * 256 + threadIdx.x;
    float val = rnd_tf32(PV[i] - 1e9f * SUF[i]);
    int dh = (int)(i & 127);
    long long t = i >> 7;
    int s = (int)(t & 2047);
    t >>= 11;
    int h = (int)(t & 15);
    int b = (int)(t >> 4);
    X[(((long long)b * SN + s) * DN) + h * DHN + dh] = val;
}

// ---------------- launch ----------------
extern "C" void kernel_launch(void* const* d_in, const int* in_sizes, int n_in,
                              void* d_out, int out_size)
{
    const float* q  = (const float*)d_in[0];
    const float* k  = (const float*)d_in[1];
    const float* v  = (const float*)d_in[2];
    const float* Wq = (const float*)d_in[3];
    const float* bq = (const float*)d_in[4];
    const float* Wk = (const float*)d_in[5];
    const float* bk = (const float*)d_in[6];
    const float* Wv = (const float*)d_in[7];
    const float* bv = (const float*)d_in[8];
    const float* Wo = (const float*)d_in[9];
    const float* bo = (const float*)d_in[10];
    float* out = (float*)d_out;

    void *p;
    float *qr, *kr, *vr, *Wtq, *Wtk, *Wtv, *Wto, *Qh, *Kh, *Vh, *Vt, *P, *PV, *SEG, *SUF, *X;
    cudaGetSymbolAddress(&p, g_qr);  qr  = (float*)p;
    cudaGetSymbolAddress(&p, g_kr);  kr  = (float*)p;
    cudaGetSymbolAddress(&p, g_vr);  vr  = (float*)p;
    cudaGetSymbolAddress(&p, g_Wtq); Wtq = (float*)p;
    cudaGetSymbolAddress(&p, g_Wtk); Wtk = (float*)p;
    cudaGetSymbolAddress(&p, g_Wtv); Wtv = (float*)p;
    cudaGetSymbolAddress(&p, g_Wto); Wto = (float*)p;
    cudaGetSymbolAddress(&p, g_Q);   Qh  = (float*)p;
    cudaGetSymbolAddress(&p, g_K);   Kh  = (float*)p;
    cudaGetSymbolAddress(&p, g_Vh);  Vh  = (float*)p;
    cudaGetSymbolAddress(&p, g_Vt);  Vt  = (float*)p;
    cudaGetSymbolAddress(&p, g_P);   P   = (float*)p;
    cudaGetSymbolAddress(&p, g_PV);  PV  = (float*)p;
    cudaGetSymbolAddress(&p, g_SEG); SEG = (float*)p;
    cudaGetSymbolAddress(&p, g_SUF); SUF = (float*)p;
    cudaGetSymbolAddress(&p, g_X);   X   = (float*)p;

    constexpr int SMEM = 65536;
    cudaFuncSetAttribute(mma_gemm<0>, cudaFuncAttributeMaxDynamicSharedMemorySize, SMEM);
    cudaFuncSetAttribute(mma_gemm<1>, cudaFuncAttributeMaxDynamicSharedMemorySize, SMEM);
    cudaFuncSetAttribute(mma_gemm<2>, cudaFuncAttributeMaxDynamicSharedMemorySize, SMEM);
    cudaFuncSetAttribute(mma_gemm<3>, cudaFuncAttributeMaxDynamicSharedMemorySize, SMEM);
    cudaFuncSetAttribute(mma_gemm<4>, cudaFuncAttributeMaxDynamicSharedMemorySize, SMEM);

    // 0) round inputs to tf32; transpose+round weights
    round_copy<<<(MR * DN) / 1024, 256>>>(q, qr);
    round_copy<<<(MR * DN) / 1024, 256>>>(k, kr);
    round_copy<<<(MR * DN) / 1024, 256>>>(v, vr);
    dim3 gT(DN / 32, DN / 32);
    transpose_round<<<gT, 256>>>(Wq, Wtq);
    transpose_round<<<gT, 256>>>(Wk, Wtk);
    transpose_round<<<gT, 256>>>(Wv, Wtv);
    transpose_round<<<gT, 256>>>(Wo, Wto);

    // 1) projections
    dim3 gProj(DN / 128, MR / 128, 1);   // (16, 64)
    mma_gemm<1><<<gProj, 256, SMEM>>>(qr, Wtq, bq, Qh, nullptr, DN, DN, DN, 0, 0, 1.f);
    mma_gemm<1><<<gProj, 256, SMEM>>>(kr, Wtk, bk, Kh, nullptr, DN, DN, DN, 0, 0, 1.f);
    mma_gemm<2><<<gProj, 256, SMEM>>>(vr, Wtv, bv, Vh, Vt,      DN, DN, DN, 0, 0, 1.f);

    // 2) scores = Q @ K^T / sqrt(DH)
    dim3 gSc(SN / 128, SN / 128, BH);    // (16, 16, 64)
    mma_gemm<3><<<gSc, 256, SMEM>>>(Qh, Kh, nullptr, P, nullptr,
                                    DHN, DHN, DHN,
                                    (long long)SN * DHN, (long long)SN * DHN, QK_SCALE);

    // 3) softmax + causal zero (rounded)
    softmax_causal<<<BH * SN, 256>>>(P);

    // 4) suffix sums of V
    dim3 gSuf(BH, 16);
    suf_pass1<<<gSuf, 128>>>(Vh, SEG);
    suf_pass2<<<gSuf, 128>>>(Vh, SEG, SUF);

    // 5) PV = P @ V   (B side = Vt, K-major along s)
    dim3 gPV(DHN / 128, SN / 128, BH);   // (1, 16, 64)
    mma_gemm<4><<<gPV, 256, SMEM>>>(P, Vt, nullptr, PV, nullptr,
                                    SN, SN, SN,
                                    (long long)SN * SN, (long long)DHN * SN, 1.f);

    // 6) merge + suffix correction
    merge_k<<<(BH * SN * DHN) / 256, 256>>>(PV, SUF, X);

    // 7) output projection
    mma_gemm<0><<<gProj, 256, SMEM>>>(X, Wto, bo, out, nullptr, DN, DN, DN, 0, 0, 1.f);
}

// round 5
// speedup vs baseline: 6.8804x; 1.5089x over previous
#include <cuda_runtime.h>
#include <cuda_fp16.h>
#include <cstdint>
#include <math.h>

// ---------------- problem constants ----------------
constexpr int BN  = 4;
constexpr int SN  = 2048;
constexpr int DN  = 2048;
constexpr int HN  = 16;
constexpr int DHN = 128;
constexpr int BH  = BN * HN;      // 64
constexpr int MR  = BN * SN;      // 8192
constexpr float QK_SCALE = 0.08838834764831845f;

// ---------------- static device scratch ----------------
__device__ __half g_qh [(size_t)MR * DN];
__device__ __half g_kh [(size_t)MR * DN];
__device__ __half g_vh [(size_t)MR * DN];
__device__ __half g_Wtq[(size_t)DN * DN];
__device__ __half g_Wtk[(size_t)DN * DN];
__device__ __half g_Wtv[(size_t)DN * DN];
__device__ __half g_Wto[(size_t)DN * DN];
__device__ __half g_Q  [(size_t)BH * SN * DHN];   // [bh,s,dh] fp16
__device__ __half g_K  [(size_t)BH * SN * DHN];
__device__ __half g_Vt [(size_t)BH * DHN * SN];   // [bh,dh,s] fp16
__device__ __half g_Vm [(size_t)MR * DN];         // merged V proj [B,S,D] fp16
__device__ float  g_P  [(size_t)BH * SN * SN];    // scores fp32, 1 GiB
__device__ __half g_Ph [(size_t)BH * SN * SN];    // probs fp16, 512 MB
__device__ __half g_PVm[(size_t)MR * DN];         // merged PV [B,S,D] fp16
__device__ float  g_U  [(size_t)MR * DN];         // Vm @ Wo, fp32
__device__ float  g_SUF[(size_t)MR * DN];         // suffix sums of U, fp32
__device__ float  g_SEG[(size_t)BN * 16 * DN];

// ---------------- helpers ----------------
__device__ __forceinline__ uint32_t smem_u32(const void* p) {
    uint32_t a;
    asm("{ .reg .u64 t; cvta.to.shared.u64 t, %1; cvt.u32.u64 %0, t; }" : "=r"(a) : "l"(p));
    return a;
}
__device__ __forceinline__ void cp_async16(uint32_t dst, const void* src) {
    asm volatile("cp.async.cg.shared.global [%0], [%1], 16;" :: "r"(dst), "l"(src));
}
__device__ __forceinline__ void cp_commit() { asm volatile("cp.async.commit_group;"); }
__device__ __forceinline__ void cp_wait0()  { asm volatile("cp.async.wait_group 0;"); }
__device__ __forceinline__ void cp_wait1()  { asm volatile("cp.async.wait_group 1;"); }
__device__ __forceinline__ uint32_t swz(uint32_t off) {
    return off ^ ((off >> 3) & 0x70);
}
__device__ __forceinline__ void ldsm4(uint32_t& r0, uint32_t& r1, uint32_t& r2, uint32_t& r3,
                                      uint32_t addr) {
    asm volatile("ldmatrix.sync.aligned.m8n8.x4.shared.b16 {%0,%1,%2,%3}, [%4];"
        : "=r"(r0), "=r"(r1), "=r"(r2), "=r"(r3) : "r"(addr));
}
__device__ __forceinline__ void mma_16816(float* c, const uint32_t* a, const uint32_t* b) {
    asm volatile("mma.sync.aligned.m16n8k16.row.col.f32.f16.f16.f32 "
        "{%0,%1,%2,%3},{%4,%5,%6,%7},{%8,%9},{%0,%1,%2,%3};"
        : "+f"(c[0]), "+f"(c[1]), "+f"(c[2]), "+f"(c[3])
        : "r"(a[0]), "r"(a[1]), "r"(a[2]), "r"(a[3]), "r"(b[0]), "r"(b[1]));
}

// ---------------- fp16 mma.sync GEMM ----------------
// D[m,n] = scale * sum_k A[m,k] * B[n,k]   (A,B fp16 K-major)
// CTA tile 128x128, K chunk 64 halves (128B rows). 8 warps (2x4), warp 64x32.
// EPI: 0 out(+bias, -1e9*suf, fp32), 1 QK-proj(+bias, head fp16),
//      2 V-proj(+bias, Vt + Vm fp16), 3 scores(*scale, fp32 batched),
//      4 PV(merged fp16, batched), 5 U(fp32)
template<int EPI>
__global__ void __launch_bounds__(256, 2)
hgemm(const __half* __restrict__ A, const __half* __restrict__ Bm,
      const float* __restrict__ bias, const float* __restrict__ suf,
      void* __restrict__ Cv, __half* __restrict__ C2,
      int K, int lda, int ldb, long long sA, long long sB, float scale)
{
    extern __shared__ char smem[];
    const uint32_t sb = smem_u32(smem);
    // A bufs [0,16K),[16K,32K); B bufs [32K,48K),[48K,64K)
    const int tid = threadIdx.x, wid = tid >> 5, lane = tid & 31;
    const int wm = wid >> 2, wn = wid & 3;
    const int m0 = blockIdx.y * 128, n0 = blockIdx.x * 128;
    const __half* Ab = A  + (long long)blockIdx.z * sA;
    const __half* Bb = Bm + (long long)blockIdx.z * sB;

    float acc[64];
#pragma unroll
    for (int i = 0; i < 64; i++) acc[i] = 0.f;

    const int CC = K >> 6;   // 64-half chunks

    auto load_chunk = [&](int buf, int c) {
        int k0 = c << 6;
#pragma unroll
        for (int i = 0; i < 4; i++) {            // A: 128 rows x 8 x 16B
            int u = tid + i * 256;
            int r = u >> 3, ku = u & 7;
            cp_async16(sb + buf * 16384 + swz(r * 128 + ku * 16),
                       Ab + (size_t)(m0 + r) * lda + k0 + ku * 8);
        }
#pragma unroll
        for (int i = 0; i < 4; i++) {            // B
            int u = tid + i * 256;
            int r = u >> 3, ku = u & 7;
            cp_async16(sb + 32768 + buf * 16384 + swz(r * 128 + ku * 16),
                       Bb + (size_t)(n0 + r) * ldb + k0 + ku * 8);
        }
        cp_commit();
    };

    // fragment addressing
    const int row16 = lane & 15;
    const int aKh   = (lane >> 4) & 1;           // +16B k for mats 2,3
    uint32_t aBase[4], aSx[4];
#pragma unroll
    for (int mt = 0; mt < 4; mt++) {
        int m = wm * 64 + mt * 16 + row16;
        aBase[mt] = m * 128;
        aSx[mt] = (m & 7) << 4;
    }
    const int bKh   = (lane >> 3) & 1;
    const int bN8   = (lane >> 4) & 1;
    uint32_t bBase[2], bSx[2];
#pragma unroll
    for (int p = 0; p < 2; p++) {
        int n = wn * 32 + p * 16 + bN8 * 8 + (lane & 7);
        bBase[p] = 32768 + n * 128;
        bSx[p] = (n & 7) << 4;
    }

    load_chunk(0, 0);
    for (int c = 0; c < CC; c++) {
        if (c + 1 < CC) { load_chunk((c + 1) & 1, c + 1); cp_wait1(); }
        else            { cp_wait0(); }
        __syncthreads();
        const uint32_t buf = sb + (c & 1) * 16384;
#pragma unroll
        for (int kk = 0; kk < 4; kk++) {
            uint32_t a[4][4];
            const uint32_t kofA = ((uint32_t)(kk << 5)) | (aKh << 4);
#pragma unroll
            for (int mt = 0; mt < 4; mt++)
                ldsm4(a[mt][0], a[mt][1], a[mt][2], a[mt][3],
                      buf + aBase[mt] + (kofA ^ aSx[mt]));
            uint32_t b[4][2];
            const uint32_t kofB = ((uint32_t)(kk << 5)) | (bKh << 4);
#pragma unroll
            for (int p = 0; p < 2; p++) {
                uint32_t r0, r1, r2, r3;
                ldsm4(r0, r1, r2, r3, buf + bBase[p] + (kofB ^ bSx[p]));
                b[p * 2 + 0][0] = r0; b[p * 2 + 0][1] = r1;
                b[p * 2 + 1][0] = r2; b[p * 2 + 1][1] = r3;
            }
#pragma unroll
            for (int mt = 0; mt < 4; mt++)
#pragma unroll
                for (int nt = 0; nt < 4; nt++)
                    mma_16816(&acc[(mt * 4 + nt) * 4], a[mt], b[nt]);
        }
        __syncthreads();
    }

    // epilogue
    const int gid = lane >> 2, tig = lane & 3;
    auto store2 = [&](int m, int n, float x, float y) {
        if (EPI == 0) {
            float2 bb = *(const float2*)(bias + n);
            const float* sf = suf + (size_t)m * DN + n;
            float* C = (float*)Cv;
            *(float2*)(C + (size_t)m * DN + n) =
                make_float2(x + bb.x - 1e9f * sf[0], y + bb.y - 1e9f * sf[1]);
        } else if (EPI == 1 || EPI == 2) {
            float2 bb = *(const float2*)(bias + n);
            float vx = x + bb.x, vy = y + bb.y;
            int bi = m >> 11, s = m & 2047;
            int h = n >> 7, dh = n & 127;
            size_t hb = (size_t)(bi * HN + h);
            __half* C = (__half*)Cv;
            if (EPI == 1) {
                *(__half2*)(C + (hb * SN + s) * DHN + dh) = __floats2half2_rn(vx, vy);
            } else {
                // Vm merged [B,S,D]
                *(__half2*)(C + (size_t)m * DN + n) = __floats2half2_rn(vx, vy);
                // Vt [bh, dh, s]
                C2[(hb * DHN + dh + 0) * SN + s] = __float2half_rn(vx);
                C2[(hb * DHN + dh + 1) * SN + s] = __float2half_rn(vy);
            }
        } else if (EPI == 3) {
            float* C = (float*)Cv;
            *(float2*)(C + (size_t)blockIdx.z * SN * SN + (size_t)m * SN + n) =
                make_float2(x * scale, y * scale);
        } else if (EPI == 4) {
            int b = blockIdx.z >> 4, h = blockIdx.z & 15;
            __half* C = (__half*)Cv;
            *(__half2*)(C + ((size_t)(b * SN + m) * DN) + h * DHN + n) =
                __floats2half2_rn(x, y);
        } else {  // EPI 5: U fp32
            float* C = (float*)Cv;
            *(float2*)(C + (size_t)m * DN + n) = make_float2(x, y);
        }
    };
#pragma unroll
    for (int mt = 0; mt < 4; mt++) {
        int m = m0 + wm * 64 + mt * 16 + gid;
#pragma unroll
        for (int nt = 0; nt < 4; nt++) {
            int n = n0 + wn * 32 + nt * 8 + 2 * tig;
            const float* cc = &acc[(mt * 4 + nt) * 4];
            store2(m,     n, cc[0], cc[1]);
            store2(m + 8, n, cc[2], cc[3]);
        }
    }
}

// ---------------- fp32 -> fp16 conversion ----------------
__global__ void __launch_bounds__(256)
f2h(const float* __restrict__ x, __half* __restrict__ y)
{
    int i = blockIdx.x * 256 + threadIdx.x;
    float4 v = ((const float4*)x)[i];
    __half2 h0 = __floats2half2_rn(v.x, v.y);
    __half2 h1 = __floats2half2_rn(v.z, v.w);
    ((uint2*)y)[i] = make_uint2(*(uint32_t*)&h0, *(uint32_t*)&h1);
}

__global__ void __launch_bounds__(256)
transpose_h(const float* __restrict__ W, __half* __restrict__ Wt)
{
    __shared__ float t[32][33];
    int k0 = blockIdx.x * 32, n0 = blockIdx.y * 32;
    int tx = threadIdx.x & 31, ty = threadIdx.x >> 5;
#pragma unroll
    for (int j = ty; j < 32; j += 8)
        t[j][tx] = W[(size_t)(k0 + j) * DN + n0 + tx];
    __syncthreads();
#pragma unroll
    for (int j = ty; j < 32; j += 8)
        Wt[(size_t)(n0 + j) * DN + k0 + tx] = __float2half_rn(t[tx][j]);
}

// ---------------- full-row softmax (fp32 in) + causal zero -> fp16 ----------------
__global__ void __launch_bounds__(256)
softmax_causal(const float* __restrict__ P, __half* __restrict__ Ph)
{
    long long row = blockIdx.x;
    int q = (int)(row & (SN - 1));
    const float* p = P + row * SN;
    __half* ph = Ph + row * SN;
    int tid = threadIdx.x, lane = tid & 31, wid = tid >> 5;

    float4 v0 = ((const float4*)p)[tid];
    float4 v1 = ((const float4*)p)[tid + 256];
    float mx = fmaxf(fmaxf(fmaxf(v0.x, v0.y), fmaxf(v0.z, v0.w)),
                     fmaxf(fmaxf(v1.x, v1.y), fmaxf(v1.z, v1.w)));
#pragma unroll
    for (int o = 16; o; o >>= 1) mx = fmaxf(mx, __shfl_xor_sync(0xffffffffu, mx, o));
    __shared__ float rmax[8], rsum[8];
    if (lane == 0) rmax[wid] = mx;
    __syncthreads();
    float m = fmaxf(fmaxf(fmaxf(rmax[0], rmax[1]), fmaxf(rmax[2], rmax[3])),
                    fmaxf(fmaxf(rmax[4], rmax[5]), fmaxf(rmax[6], rmax[7])));
    float e[8];
    e[0] = __expf(v0.x - m); e[1] = __expf(v0.y - m);
    e[2] = __expf(v0.z - m); e[3] = __expf(v0.w - m);
    e[4] = __expf(v1.x - m); e[5] = __expf(v1.y - m);
    e[6] = __expf(v1.z - m); e[7] = __expf(v1.w - m);
    float s = ((e[0] + e[1]) + (e[2] + e[3])) + ((e[4] + e[5]) + (e[6] + e[7]));
#pragma unroll
    for (int o = 16; o; o >>= 1) s += __shfl_xor_sync(0xffffffffu, s, o);
    if (lane == 0) rsum[wid] = s;
    __syncthreads();
    float tot = ((rsum[0] + rsum[1]) + (rsum[2] + rsum[3])) +
                ((rsum[4] + rsum[5]) + (rsum[6] + rsum[7]));
    float inv = 1.0f / tot;

    int k0 = tid * 4, k1 = 1024 + tid * 4;
    float a0 = (k0 + 0 <= q) ? e[0] * inv : 0.f;
    float a1 = (k0 + 1 <= q) ? e[1] * inv : 0.f;
    float a2 = (k0 + 2 <= q) ? e[2] * inv : 0.f;
    float a3 = (k0 + 3 <= q) ? e[3] * inv : 0.f;
    float b0 = (k1 + 0 <= q) ? e[4] * inv : 0.f;
    float b1 = (k1 + 1 <= q) ? e[5] * inv : 0.f;
    float b2 = (k1 + 2 <= q) ? e[6] * inv : 0.f;
    float b3 = (k1 + 3 <= q) ? e[7] * inv : 0.f;
    ((__half2*)ph)[tid * 2 + 0] = __floats2half2_rn(a0, a1);
    ((__half2*)ph)[tid * 2 + 1] = __floats2half2_rn(a2, a3);
    ((__half2*)ph)[512 + tid * 2 + 0] = __floats2half2_rn(b0, b1);
    ((__half2*)ph)[512 + tid * 2 + 1] = __floats2half2_rn(b2, b3);
}

// ---------------- suffix sums of U over s (per batch, per d) ----------------
__global__ void __launch_bounds__(256)
suf_pass1(const float* __restrict__ U, float* __restrict__ seg)
{
    int b = blockIdx.x, sg = blockIdx.y;
    int d = blockIdx.z * 256 + threadIdx.x;
    const float* u = U + ((size_t)b * SN + sg * 128) * DN + d;
    float a = 0.f;
#pragma unroll 8
    for (int i = 0; i < 128; i++) a += u[(size_t)i * DN];
    seg[((size_t)b * 16 + sg) * DN + d] = a;
}

__global__ void __launch_bounds__(256)
suf_pass2(const float* __restrict__ U, const float* __restrict__ seg,
          float* __restrict__ SUF)
{
    int b = blockIdx.x, sg = blockIdx.y;
    int d = blockIdx.z * 256 + threadIdx.x;
    float off = 0.f;
    for (int j = sg + 1; j < 16; j++) off += seg[((size_t)b * 16 + j) * DN + d];
    const float* u = U + ((size_t)b * SN + sg * 128) * DN + d;
    float* o = SUF + ((size_t)b * SN + sg * 128) * DN + d;
    float a = off;
    for (int i = 127; i >= 0; i--) {
        o[(size_t)i * DN] = a;
        a += u[(size_t)i * DN];
    }
}

// ---------------- launch ----------------
extern "C" void kernel_launch(void* const* d_in, const int* in_sizes, int n_in,
                              void* d_out, int out_size)
{
    const float* q  = (const float*)d_in[0];
    const float* k  = (const float*)d_in[1];
    const float* v  = (const float*)d_in[2];
    const float* Wq = (const float*)d_in[3];
    const float* bq = (const float*)d_in[4];
    const float* Wk = (const float*)d_in[5];
    const float* bk = (const float*)d_in[6];
    const float* Wv = (const float*)d_in[7];
    const float* bv = (const float*)d_in[8];
    const float* Wo = (const float*)d_in[9];
    const float* bo = (const float*)d_in[10];
    float* out = (float*)d_out;

    void *p;
    __half *qh, *kh, *vh, *Wtq, *Wtk, *Wtv, *Wto, *Qh, *Kh, *Vt, *Vm, *Ph, *PVm;
    float *P, *U, *SUF, *SEG;
    cudaGetSymbolAddress(&p, g_qh);  qh  = (__half*)p;
    cudaGetSymbolAddress(&p, g_kh);  kh  = (__half*)p;
    cudaGetSymbolAddress(&p, g_vh);  vh  = (__half*)p;
    cudaGetSymbolAddress(&p, g_Wtq); Wtq = (__half*)p;
    cudaGetSymbolAddress(&p, g_Wtk); Wtk = (__half*)p;
    cudaGetSymbolAddress(&p, g_Wtv); Wtv = (__half*)p;
    cudaGetSymbolAddress(&p, g_Wto); Wto = (__half*)p;
    cudaGetSymbolAddress(&p, g_Q);   Qh  = (__half*)p;
    cudaGetSymbolAddress(&p, g_K);   Kh  = (__half*)p;
    cudaGetSymbolAddress(&p, g_Vt);  Vt  = (__half*)p;
    cudaGetSymbolAddress(&p, g_Vm);  Vm  = (__half*)p;
    cudaGetSymbolAddress(&p, g_P);   P   = (float*)p;
    cudaGetSymbolAddress(&p, g_Ph);  Ph  = (__half*)p;
    cudaGetSymbolAddress(&p, g_PVm); PVm = (__half*)p;
    cudaGetSymbolAddress(&p, g_U);   U   = (float*)p;
    cudaGetSymbolAddress(&p, g_SUF); SUF = (float*)p;
    cudaGetSymbolAddress(&p, g_SEG); SEG = (float*)p;

    constexpr int SMEM = 65536;
    cudaFuncSetAttribute(hgemm<0>, cudaFuncAttributeMaxDynamicSharedMemorySize, SMEM);
    cudaFuncSetAttribute(hgemm<1>, cudaFuncAttributeMaxDynamicSharedMemorySize, SMEM);
    cudaFuncSetAttribute(hgemm<2>, cudaFuncAttributeMaxDynamicSharedMemorySize, SMEM);
    cudaFuncSetAttribute(hgemm<3>, cudaFuncAttributeMaxDynamicSharedMemorySize, SMEM);
    cudaFuncSetAttribute(hgemm<4>, cudaFuncAttributeMaxDynamicSharedMemorySize, SMEM);
    cudaFuncSetAttribute(hgemm<5>, cudaFuncAttributeMaxDynamicSharedMemorySize, SMEM);

    // 0) convert inputs / weights to fp16 (weights transposed)
    f2h<<<(MR * DN) / 1024, 256>>>(q, qh);
    f2h<<<(MR * DN) / 1024, 256>>>(k, kh);
    f2h<<<(MR * DN) / 1024, 256>>>(v, vh);
    dim3 gT(DN / 32, DN / 32);
    transpose_h<<<gT, 256>>>(Wq, Wtq);
    transpose_h<<<gT, 256>>>(Wk, Wtk);
    transpose_h<<<gT, 256>>>(Wv, Wtv);
    transpose_h<<<gT, 256>>>(Wo, Wto);

    // 1) projections
    dim3 gProj(DN / 128, MR / 128, 1);   // (16, 64)
    hgemm<1><<<gProj, 256, SMEM>>>(qh, Wtq, bq, nullptr, Qh, nullptr, DN, DN, DN, 0, 0, 1.f);
    hgemm<1><<<gProj, 256, SMEM>>>(kh, Wtk, bk, nullptr, Kh, nullptr, DN, DN, DN, 0, 0, 1.f);
    hgemm<2><<<gProj, 256, SMEM>>>(vh, Wtv, bv, nullptr, Vm, Vt,      DN, DN, DN, 0, 0, 1.f);

    // 2) U = Vm @ Wo  (for the post-softmax mask correction), then suffix sums
    hgemm<5><<<gProj, 256, SMEM>>>(Vm, Wto, nullptr, nullptr, U, nullptr, DN, DN, DN, 0, 0, 1.f);
    dim3 gSuf(BN, 16, DN / 256);
    suf_pass1<<<gSuf, 256>>>(U, SEG);
    suf_pass2<<<gSuf, 256>>>(U, SEG, SUF);

    // 3) scores = Q @ K^T / sqrt(DH)  (fp32 out)
    dim3 gSc(SN / 128, SN / 128, BH);
    hgemm<3><<<gSc, 256, SMEM>>>(Qh, Kh, nullptr, nullptr, P, nullptr,
                                 DHN, DHN, DHN,
                                 (long long)SN * DHN, (long long)SN * DHN, QK_SCALE);

    // 4) softmax + causal zero -> fp16 probs
    softmax_causal<<<BH * SN, 256>>>(P, Ph);

    // 5) PV = Ph @ V -> merged [B,S,D] fp16
    dim3 gPV(DHN / 128, SN / 128, BH);
    hgemm<4><<<gPV, 256, SMEM>>>(Ph, Vt, nullptr, nullptr, PVm, nullptr,
                                 SN, SN, SN,
                                 (long long)SN * SN, (long long)DHN * SN, 1.f);

    // 6) out = PVm @ Wo + bo - 1e9 * SUF
    hgemm<0><<<gProj, 256, SMEM>>>(PVm, Wto, bo, SUF, out, nullptr, DN, DN, DN, 0, 0, 1.f);
}

// round 6
// speedup vs baseline: 8.2446x; 1.1983x over previous
#include <cuda_runtime.h>
#include <cuda_fp16.h>
#include <cstdint>
#include <math.h>

// ---------------- problem constants ----------------
constexpr int BN  = 4;
constexpr int SN  = 2048;
constexpr int DN  = 2048;
constexpr int HN  = 16;
constexpr int DHN = 128;
constexpr int BH  = BN * HN;      // 64
constexpr int MR  = BN * SN;      // 8192
constexpr float QK_SCALE = 0.08838834764831845f;

// ---------------- static device scratch ----------------
__device__ __half g_qh [(size_t)MR * DN];
__device__ __half g_kh [(size_t)MR * DN];
__device__ __half g_vh [(size_t)MR * DN];
__device__ __half g_Wtq[(size_t)DN * DN];
__device__ __half g_Wtk[(size_t)DN * DN];
__device__ __half g_Wtv[(size_t)DN * DN];
__device__ __half g_Wto[(size_t)DN * DN];
__device__ __half g_Q  [(size_t)BH * SN * DHN];   // [bh,s,dh] fp16 (pre-scaled by QK_SCALE)
__device__ __half g_K  [(size_t)BH * SN * DHN];   // [bh,s,dh]
__device__ __half g_Vt [(size_t)BH * DHN * SN];   // [bh,dh,s]
__device__ __half g_Vm [(size_t)MR * DN];         // merged V proj [B,S,D]
__device__ __half g_PVm[(size_t)MR * DN];         // merged PV [B,S,D]
__device__ float  g_U  [(size_t)MR * DN];         // Vm @ Wo
__device__ float  g_SUF[(size_t)MR * DN];         // suffix sums of U
__device__ float  g_SEG[(size_t)BN * 16 * DN];

// ---------------- helpers ----------------
__device__ __forceinline__ uint32_t smem_u32(const void* p) {
    uint32_t a;
    asm("{ .reg .u64 t; cvta.to.shared.u64 t, %1; cvt.u32.u64 %0, t; }" : "=r"(a) : "l"(p));
    return a;
}
__device__ __forceinline__ void cp_async16(uint32_t dst, const void* src) {
    asm volatile("cp.async.cg.shared.global [%0], [%1], 16;" :: "r"(dst), "l"(src));
}
__device__ __forceinline__ void cp_commit() { asm volatile("cp.async.commit_group;"); }
__device__ __forceinline__ void cp_wait0()  { asm volatile("cp.async.wait_group 0;"); }
__device__ __forceinline__ void cp_wait1()  { asm volatile("cp.async.wait_group 1;"); }
__device__ __forceinline__ uint32_t swz(uint32_t off) {
    return off ^ ((off >> 3) & 0x70);
}
__device__ __forceinline__ void ldsm4(uint32_t& r0, uint32_t& r1, uint32_t& r2, uint32_t& r3,
                                      uint32_t addr) {
    asm volatile("ldmatrix.sync.aligned.m8n8.x4.shared.b16 {%0,%1,%2,%3}, [%4];"
        : "=r"(r0), "=r"(r1), "=r"(r2), "=r"(r3) : "r"(addr));
}
__device__ __forceinline__ void mma_16816(float* c, const uint32_t* a, const uint32_t* b) {
    asm volatile("mma.sync.aligned.m16n8k16.row.col.f32.f16.f16.f32 "
        "{%0,%1,%2,%3},{%4,%5,%6,%7},{%8,%9},{%0,%1,%2,%3};"
        : "+f"(c[0]), "+f"(c[1]), "+f"(c[2]), "+f"(c[3])
        : "r"(a[0]), "r"(a[1]), "r"(a[2]), "r"(a[3]), "r"(b[0]), "r"(b[1]));
}

// ---------------- fp16 mma.sync GEMM ----------------
// EPI: 0 out(+bias, -1e9*suf, fp32), 1 QK-proj(+bias, *scale, head fp16),
//      2 V-proj(+bias, Vt + Vm fp16), 5 U(fp32)
template<int EPI>
__global__ void __launch_bounds__(256, 2)
hgemm(const __half* __restrict__ A, const __half* __restrict__ Bm,
      const float* __restrict__ bias, const float* __restrict__ suf,
      void* __restrict__ Cv, __half* __restrict__ C2,
      int K, int lda, int ldb, long long sA, long long sB, float scale)
{
    extern __shared__ char smem[];
    const uint32_t sb = smem_u32(smem);
    const int tid = threadIdx.x, wid = tid >> 5, lane = tid & 31;
    const int wm = wid >> 2, wn = wid & 3;
    const int m0 = blockIdx.y * 128, n0 = blockIdx.x * 128;
    const __half* Ab = A  + (long long)blockIdx.z * sA;
    const __half* Bb = Bm + (long long)blockIdx.z * sB;

    float acc[64];
#pragma unroll
    for (int i = 0; i < 64; i++) acc[i] = 0.f;

    const int CC = K >> 6;

    auto load_chunk = [&](int buf, int c) {
        int k0 = c << 6;
#pragma unroll
        for (int i = 0; i < 4; i++) {
            int u = tid + i * 256;
            int r = u >> 3, ku = u & 7;
            cp_async16(sb + buf * 16384 + swz(r * 128 + ku * 16),
                       Ab + (size_t)(m0 + r) * lda + k0 + ku * 8);
        }
#pragma unroll
        for (int i = 0; i < 4; i++) {
            int u = tid + i * 256;
            int r = u >> 3, ku = u & 7;
            cp_async16(sb + 32768 + buf * 16384 + swz(r * 128 + ku * 16),
                       Bb + (size_t)(n0 + r) * ldb + k0 + ku * 8);
        }
        cp_commit();
    };

    const int row16 = lane & 15;
    const int aKh   = (lane >> 4) & 1;
    uint32_t aBase[4], aSx[4];
#pragma unroll
    for (int mt = 0; mt < 4; mt++) {
        int m = wm * 64 + mt * 16 + row16;
        aBase[mt] = m * 128;
        aSx[mt] = (m & 7) << 4;
    }
    const int bKh   = (lane >> 3) & 1;
    const int bN8   = (lane >> 4) & 1;
    uint32_t bBase[2], bSx[2];
#pragma unroll
    for (int p = 0; p < 2; p++) {
        int n = wn * 32 + p * 16 + bN8 * 8 + (lane & 7);
        bBase[p] = 32768 + n * 128;
        bSx[p] = (n & 7) << 4;
    }

    load_chunk(0, 0);
    for (int c = 0; c < CC; c++) {
        if (c + 1 < CC) { load_chunk((c + 1) & 1, c + 1); cp_wait1(); }
        else            { cp_wait0(); }
        __syncthreads();
        const uint32_t buf = sb + (c & 1) * 16384;
#pragma unroll
        for (int kk = 0; kk < 4; kk++) {
            uint32_t a[4][4];
            const uint32_t kofA = ((uint32_t)(kk << 5)) | (aKh << 4);
#pragma unroll
            for (int mt = 0; mt < 4; mt++)
                ldsm4(a[mt][0], a[mt][1], a[mt][2], a[mt][3],
                      buf + aBase[mt] + (kofA ^ aSx[mt]));
            uint32_t b[4][2];
            const uint32_t kofB = ((uint32_t)(kk << 5)) | (bKh << 4);
#pragma unroll
            for (int p = 0; p < 2; p++) {
                uint32_t r0, r1, r2, r3;
                ldsm4(r0, r1, r2, r3, buf + bBase[p] + (kofB ^ bSx[p]));
                b[p * 2 + 0][0] = r0; b[p * 2 + 0][1] = r1;
                b[p * 2 + 1][0] = r2; b[p * 2 + 1][1] = r3;
            }
#pragma unroll
            for (int mt = 0; mt < 4; mt++)
#pragma unroll
                for (int nt = 0; nt < 4; nt++)
                    mma_16816(&acc[(mt * 4 + nt) * 4], a[mt], b[nt]);
        }
        __syncthreads();
    }

    const int gid = lane >> 2, tig = lane & 3;
    auto store2 = [&](int m, int n, float x, float y) {
        if (EPI == 0) {
            float2 bb = *(const float2*)(bias + n);
            const float* sf = suf + (size_t)m * DN + n;
            float* C = (float*)Cv;
            *(float2*)(C + (size_t)m * DN + n) =
                make_float2(x + bb.x - 1e9f * sf[0], y + bb.y - 1e9f * sf[1]);
        } else if (EPI == 1 || EPI == 2) {
            float2 bb = *(const float2*)(bias + n);
            float vx = (x + bb.x) * scale, vy = (y + bb.y) * scale;
            int bi = m >> 11, s = m & 2047;
            int h = n >> 7, dh = n & 127;
            size_t hb = (size_t)(bi * HN + h);
            __half* C = (__half*)Cv;
            if (EPI == 1) {
                *(__half2*)(C + (hb * SN + s) * DHN + dh) = __floats2half2_rn(vx, vy);
            } else {
                *(__half2*)(C + (size_t)m * DN + n) = __floats2half2_rn(vx, vy);
                C2[(hb * DHN + dh + 0) * SN + s] = __float2half_rn(vx);
                C2[(hb * DHN + dh + 1) * SN + s] = __float2half_rn(vy);
            }
        } else {  // EPI 5
            float* C = (float*)Cv;
            *(float2*)(C + (size_t)m * DN + n) = make_float2(x, y);
        }
    };
#pragma unroll
    for (int mt = 0; mt < 4; mt++) {
        int m = m0 + wm * 64 + mt * 16 + gid;
#pragma unroll
        for (int nt = 0; nt < 4; nt++) {
            int n = n0 + wn * 32 + nt * 8 + 2 * tig;
            const float* cc = &acc[(mt * 4 + nt) * 4];
            store2(m,     n, cc[0], cc[1]);
            store2(m + 8, n, cc[2], cc[3]);
        }
    }
}

// ---------------- flash attention: scores + full-row softmax + causal PV ----------------
// grid (qt=16, bh=64). 8 warps x 16 q-rows. Bc=64 kv per iter, 32 iters.
// smem: Q 32K (2 subtiles), K double-buffered 2x16K (2 subtiles each), V 2x16K.
constexpr int FL_SMEM = 98304;

__global__ void __launch_bounds__(256, 1)
flash_attn(const __half* __restrict__ Qg, const __half* __restrict__ Kg,
           const __half* __restrict__ Vtg, __half* __restrict__ PVm)
{
    extern __shared__ char smem[];
    const uint32_t sb = smem_u32(smem);
    constexpr uint32_t QS = 0, KS = 32768, VS = 65536;
    const int tid = threadIdx.x, wid = tid >> 5, lane = tid & 31;
    const int qt = blockIdx.x, bh = blockIdx.y;
    const int b = bh >> 4, h = bh & 15;
    const __half* Qp = Qg  + (size_t)bh * SN * DHN;
    const __half* Kp = Kg  + (size_t)bh * SN * DHN;
    const __half* Vp = Vtg + (size_t)bh * DHN * SN;

    // Q tile: 128 rows x 128 dh (2 subtiles of 64 dh)
#pragma unroll
    for (int i = 0; i < 8; i++) {
        int u = tid + i * 256;
        int r = u >> 4, ku = u & 15;
        cp_async16(sb + QS + (ku >> 3) * 16384 + swz(r * 128 + (ku & 7) * 16),
                   Qp + (size_t)(qt * 128 + r) * DHN + ku * 8);
    }
    auto loadK = [&](int kt, int buf) {
#pragma unroll
        for (int i = 0; i < 4; i++) {
            int u = tid + i * 256;
            int r = u >> 4, ku = u & 15;
            cp_async16(sb + KS + buf * 16384 + (ku >> 3) * 8192 + swz(r * 128 + (ku & 7) * 16),
                       Kp + (size_t)(kt * 64 + r) * DHN + ku * 8);
        }
    };
    auto loadV = [&](int kt, int buf) {
#pragma unroll
        for (int i = 0; i < 4; i++) {
            int u = tid + i * 256;
            int r = u >> 3, ku = u & 7;
            cp_async16(sb + VS + buf * 16384 + swz(r * 128 + ku * 16),
                       Vp + (size_t)r * SN + kt * 64 + ku * 8);
        }
    };
    loadK(0, 0); loadV(0, 0); cp_commit();

    const int gid = lane >> 2, tig = lane & 3;
    const int am = wid * 16 + (lane & 15);
    const int aKh = (lane >> 4) & 1;
    const uint32_t aBase = am * 128, aSx = (am & 7) << 4;
    const int bKh = (lane >> 3) & 1, bN8 = (lane >> 4) & 1;

    const int q0 = qt * 128 + wid * 16 + gid;
    const int q1 = q0 + 8;
    const int qmaxw = qt * 128 + wid * 16 + 15;

    float m0r = -1e30f, m1r = -1e30f, l0 = 0.f, l1 = 0.f;
    float oacc[16][4];
#pragma unroll
    for (int i = 0; i < 16; i++)
#pragma unroll
        for (int j = 0; j < 4; j++) oacc[i][j] = 0.f;

    for (int kt = 0; kt < 32; kt++) {
        const int buf = kt & 1;
        if (kt + 1 < 32) { loadK(kt + 1, buf ^ 1); loadV(kt + 1, buf ^ 1); cp_commit(); cp_wait1(); }
        else             { cp_wait0(); }
        __syncthreads();

        // S = Q @ K^T  (16 x 64 per warp), fp32 accum
        float sacc[8][4];
#pragma unroll
        for (int nt = 0; nt < 8; nt++)
#pragma unroll
            for (int j = 0; j < 4; j++) sacc[nt][j] = 0.f;
#pragma unroll
        for (int kk = 0; kk < 8; kk++) {
            uint32_t a[4];
            const uint32_t kofA = ((uint32_t)((kk & 3) << 5)) | (aKh << 4);
            ldsm4(a[0], a[1], a[2], a[3],
                  sb + QS + (kk >> 2) * 16384 + aBase + (kofA ^ aSx));
            const uint32_t kofB = ((uint32_t)((kk & 3) << 5)) | (bKh << 4);
            const uint32_t kb = sb + KS + buf * 16384 + (kk >> 2) * 8192;
#pragma unroll
            for (int p = 0; p < 4; p++) {
                int n = p * 16 + bN8 * 8 + (lane & 7);
                uint32_t r0, r1, r2, r3;
                ldsm4(r0, r1, r2, r3, kb + n * 128 + (kofB ^ ((n & 7) << 4)));
                uint32_t b0[2] = {r0, r1}, b1[2] = {r2, r3};
                mma_16816(sacc[p * 2 + 0], a, b0);
                mma_16816(sacc[p * 2 + 1], a, b1);
            }
        }

        // online softmax (full row: all kv contribute to m and l)
        float mx0 = -1e30f, mx1 = -1e30f;
#pragma unroll
        for (int nt = 0; nt < 8; nt++) {
            mx0 = fmaxf(mx0, fmaxf(sacc[nt][0], sacc[nt][1]));
            mx1 = fmaxf(mx1, fmaxf(sacc[nt][2], sacc[nt][3]));
        }
        mx0 = fmaxf(mx0, __shfl_xor_sync(0xffffffffu, mx0, 1));
        mx0 = fmaxf(mx0, __shfl_xor_sync(0xffffffffu, mx0, 2));
        mx1 = fmaxf(mx1, __shfl_xor_sync(0xffffffffu, mx1, 1));
        mx1 = fmaxf(mx1, __shfl_xor_sync(0xffffffffu, mx1, 2));
        float mn0 = fmaxf(m0r, mx0), mn1 = fmaxf(m1r, mx1);
        float sc0 = __expf(m0r - mn0), sc1 = __expf(m1r - mn1);
        m0r = mn0; m1r = mn1;
        l0 *= sc0; l1 *= sc1;
#pragma unroll
        for (int nt = 0; nt < 16; nt++) {
            oacc[nt][0] *= sc0; oacc[nt][1] *= sc0;
            oacc[nt][2] *= sc1; oacc[nt][3] *= sc1;
        }
        const int kvb = kt * 64;
        uint32_t pf[8][2];
#pragma unroll
        for (int nt = 0; nt < 8; nt++) {
            int c0 = kvb + nt * 8 + 2 * tig, c1 = c0 + 1;
            float e0 = __expf(sacc[nt][0] - mn0), e1 = __expf(sacc[nt][1] - mn0);
            float e2 = __expf(sacc[nt][2] - mn1), e3 = __expf(sacc[nt][3] - mn1);
            l0 += e0 + e1; l1 += e2 + e3;
            __half2 h01 = __floats2half2_rn(c0 <= q0 ? e0 : 0.f, c1 <= q0 ? e1 : 0.f);
            __half2 h23 = __floats2half2_rn(c0 <= q1 ? e2 : 0.f, c1 <= q1 ? e3 : 0.f);
            pf[nt][0] = *(uint32_t*)&h01;
            pf[nt][1] = *(uint32_t*)&h23;
        }

        // PV accumulate (skip tiles fully beyond the causal frontier of this warp)
        if (kvb <= qmaxw) {
#pragma unroll
            for (int j = 0; j < 4; j++) {
                uint32_t a2[4] = { pf[2 * j][0], pf[2 * j][1], pf[2 * j + 1][0], pf[2 * j + 1][1] };
                const uint32_t kofB = ((uint32_t)(j << 5)) | (bKh << 4);
                const uint32_t vb = sb + VS + buf * 16384;
#pragma unroll
                for (int p = 0; p < 8; p++) {
                    int n = p * 16 + bN8 * 8 + (lane & 7);
                    uint32_t r0, r1, r2, r3;
                    ldsm4(r0, r1, r2, r3, vb + n * 128 + (kofB ^ ((n & 7) << 4)));
                    uint32_t b0[2] = {r0, r1}, b1[2] = {r2, r3};
                    mma_16816(oacc[p * 2 + 0], a2, b0);
                    mma_16816(oacc[p * 2 + 1], a2, b1);
                }
            }
        }
        __syncthreads();
    }

    // finalize: normalize by full-row sum, write merged [B,S,D] fp16
    l0 += __shfl_xor_sync(0xffffffffu, l0, 1);
    l0 += __shfl_xor_sync(0xffffffffu, l0, 2);
    l1 += __shfl_xor_sync(0xffffffffu, l1, 1);
    l1 += __shfl_xor_sync(0xffffffffu, l1, 2);
    const float i0 = 1.f / l0, i1 = 1.f / l1;
#pragma unroll
    for (int nt = 0; nt < 16; nt++) {
        int dh = nt * 8 + 2 * tig;
        __half2 ha = __floats2half2_rn(oacc[nt][0] * i0, oacc[nt][1] * i0);
        __half2 hb = __floats2half2_rn(oacc[nt][2] * i1, oacc[nt][3] * i1);
        *(__half2*)(PVm + ((size_t)(b * SN) + q0) * DN + h * 128 + dh) = ha;
        *(__half2*)(PVm + ((size_t)(b * SN) + q1) * DN + h * 128 + dh) = hb;
    }
}

// ---------------- fp32 -> fp16 conversion ----------------
__global__ void __launch_bounds__(256)
f2h(const float* __restrict__ x, __half* __restrict__ y)
{
    int i = blockIdx.x * 256 + threadIdx.x;
    float4 v = ((const float4*)x)[i];
    __half2 h0 = __floats2half2_rn(v.x, v.y);
    __half2 h1 = __floats2half2_rn(v.z, v.w);
    ((uint2*)y)[i] = make_uint2(*(uint32_t*)&h0, *(uint32_t*)&h1);
}

__global__ void __launch_bounds__(256)
transpose_h(const float* __restrict__ W, __half* __restrict__ Wt)
{
    __shared__ float t[32][33];
    int k0 = blockIdx.x * 32, n0 = blockIdx.y * 32;
    int tx = threadIdx.x & 31, ty = threadIdx.x >> 5;
#pragma unroll
    for (int j = ty; j < 32; j += 8)
        t[j][tx] = W[(size_t)(k0 + j) * DN + n0 + tx];
    __syncthreads();
#pragma unroll
    for (int j = ty; j < 32; j += 8)
        Wt[(size_t)(n0 + j) * DN + k0 + tx] = __float2half_rn(t[tx][j]);
}

// ---------------- suffix sums of U over s ----------------
__global__ void __launch_bounds__(256)
suf_pass1(const float* __restrict__ U, float* __restrict__ seg)
{
    int b = blockIdx.x, sg = blockIdx.y;
    int d = blockIdx.z * 256 + threadIdx.x;
    const float* u = U + ((size_t)b * SN + sg * 128) * DN + d;
    float a = 0.f;
#pragma unroll 8
    for (int i = 0; i < 128; i++) a += u[(size_t)i * DN];
    seg[((size_t)b * 16 + sg) * DN + d] = a;
}

__global__ void __launch_bounds__(256)
suf_pass2(const float* __restrict__ U, const float* __restrict__ seg,
          float* __restrict__ SUF)
{
    int b = blockIdx.x, sg = blockIdx.y;
    int d = blockIdx.z * 256 + threadIdx.x;
    float off = 0.f;
    for (int j = sg + 1; j < 16; j++) off += seg[((size_t)b * 16 + j) * DN + d];
    const float* u = U + ((size_t)b * SN + sg * 128) * DN + d;
    float* o = SUF + ((size_t)b * SN + sg * 128) * DN + d;
    float a = off;
    for (int i = 127; i >= 0; i--) {
        o[(size_t)i * DN] = a;
        a += u[(size_t)i * DN];
    }
}

// ---------------- launch ----------------
extern "C" void kernel_launch(void* const* d_in, const int* in_sizes, int n_in,
                              void* d_out, int out_size)
{
    const float* q  = (const float*)d_in[0];
    const float* k  = (const float*)d_in[1];
    const float* v  = (const float*)d_in[2];
    const float* Wq = (const float*)d_in[3];
    const float* bq = (const float*)d_in[4];
    const float* Wk = (const float*)d_in[5];
    const float* bk = (const float*)d_in[6];
    const float* Wv = (const float*)d_in[7];
    const float* bv = (const float*)d_in[8];
    const float* Wo = (const float*)d_in[9];
    const float* bo = (const float*)d_in[10];
    float* out = (float*)d_out;

    void *p;
    __half *qh, *kh, *vh, *Wtq, *Wtk, *Wtv, *Wto, *Qh, *Kh, *Vt, *Vm, *PVm;
    float *U, *SUF, *SEG;
    cudaGetSymbolAddress(&p, g_qh);  qh  = (__half*)p;
    cudaGetSymbolAddress(&p, g_kh);  kh  = (__half*)p;
    cudaGetSymbolAddress(&p, g_vh);  vh  = (__half*)p;
    cudaGetSymbolAddress(&p, g_Wtq); Wtq = (__half*)p;
    cudaGetSymbolAddress(&p, g_Wtk); Wtk = (__half*)p;
    cudaGetSymbolAddress(&p, g_Wtv); Wtv = (__half*)p;
    cudaGetSymbolAddress(&p, g_Wto); Wto = (__half*)p;
    cudaGetSymbolAddress(&p, g_Q);   Qh  = (__half*)p;
    cudaGetSymbolAddress(&p, g_K);   Kh  = (__half*)p;
    cudaGetSymbolAddress(&p, g_Vt);  Vt  = (__half*)p;
    cudaGetSymbolAddress(&p, g_Vm);  Vm  = (__half*)p;
    cudaGetSymbolAddress(&p, g_PVm); PVm = (__half*)p;
    cudaGetSymbolAddress(&p, g_U);   U   = (float*)p;
    cudaGetSymbolAddress(&p, g_SUF); SUF = (float*)p;
    cudaGetSymbolAddress(&p, g_SEG); SEG = (float*)p;

    constexpr int SMEM = 65536;
    cudaFuncSetAttribute(hgemm<0>, cudaFuncAttributeMaxDynamicSharedMemorySize, SMEM);
    cudaFuncSetAttribute(hgemm<1>, cudaFuncAttributeMaxDynamicSharedMemorySize, SMEM);
    cudaFuncSetAttribute(hgemm<2>, cudaFuncAttributeMaxDynamicSharedMemorySize, SMEM);
    cudaFuncSetAttribute(hgemm<5>, cudaFuncAttributeMaxDynamicSharedMemorySize, SMEM);
    cudaFuncSetAttribute(flash_attn, cudaFuncAttributeMaxDynamicSharedMemorySize, FL_SMEM);

    // 0) convert inputs / weights to fp16 (weights transposed)
    f2h<<<(MR * DN) / 1024, 256>>>(q, qh);
    f2h<<<(MR * DN) / 1024, 256>>>(k, kh);
    f2h<<<(MR * DN) / 1024, 256>>>(v, vh);
    dim3 gT(DN / 32, DN / 32);
    transpose_h<<<gT, 256>>>(Wq, Wtq);
    transpose_h<<<gT, 256>>>(Wk, Wtk);
    transpose_h<<<gT, 256>>>(Wv, Wtv);
    transpose_h<<<gT, 256>>>(Wo, Wto);

    // 1) projections (Q pre-scaled by 1/sqrt(DH))
    dim3 gProj(DN / 128, MR / 128, 1);
    hgemm<1><<<gProj, 256, SMEM>>>(qh, Wtq, bq, nullptr, Qh, nullptr, DN, DN, DN, 0, 0, QK_SCALE);
    hgemm<1><<<gProj, 256, SMEM>>>(kh, Wtk, bk, nullptr, Kh, nullptr, DN, DN, DN, 0, 0, 1.f);
    hgemm<2><<<gProj, 256, SMEM>>>(vh, Wtv, bv, nullptr, Vm, Vt,      DN, DN, DN, 0, 0, 1.f);

    // 2) U = Vm @ Wo, then suffix sums (post-softmax mask correction)
    hgemm<5><<<gProj, 256, SMEM>>>(Vm, Wto, nullptr, nullptr, U, nullptr, DN, DN, DN, 0, 0, 1.f);
    dim3 gSuf(BN, 16, DN / 256);
    suf_pass1<<<gSuf, 256>>>(U, SEG);
    suf_pass2<<<gSuf, 256>>>(U, SEG, SUF);

    // 3) fused attention -> merged PV [B,S,D] fp16
    dim3 gFl(SN / 128, BH);
    flash_attn<<<gFl, 256, FL_SMEM>>>(Qh, Kh, Vt, PVm);

    // 4) out = PVm @ Wo + bo - 1e9 * SUF
    hgemm<0><<<gProj, 256, SMEM>>>(PVm, Wto, bo, SUF, out, nullptr, DN, DN, DN, 0, 0, 1.f);
}